// round 1
// baseline (speedup 1.0000x reference)
#include <cuda_runtime.h>
#include <math.h>
#include <math_constants.h>

// Problem shape (fixed by the reference)
constexpr int B_ = 8;
constexpr int T_ = 2048;
constexpr int E_ = 1024;
constexpr int H_ = 64;
constexpr int MT = B_ * T_;   // 16384 rows

// Scratch for projected q,k,v (4 MB each) — device globals (no allocs allowed)
__device__ float g_q[MT * H_];
__device__ float g_k[MT * H_];
__device__ float g_v[MT * H_];

// ---------------------------------------------------------------------------
// Kernel 1: QKV projection.  out[m][h] = sum_e x[m][e] * W[h][e]
// GEMM: M=16384, N=64 (per weight), K=1024.  grid = (M/64, 3), 256 threads.
// 64x64 C tile, BK=32, 4x4 register tile per thread.
// ---------------------------------------------------------------------------
__global__ __launch_bounds__(256) void qkv_kernel(
    const float* __restrict__ x,
    const float* __restrict__ Wq,
    const float* __restrict__ Wk,
    const float* __restrict__ Wv)
{
    constexpr int BK = 32;
    __shared__ float As[BK][68];   // transposed: As[k][m]
    __shared__ float Bs[BK][68];   // transposed: Bs[k][h]

    const float* W;
    float* outp;
    if (blockIdx.y == 0)      { W = Wq; outp = g_q; }
    else if (blockIdx.y == 1) { W = Wk; outp = g_k; }
    else                      { W = Wv; outp = g_v; }

    const int m0  = blockIdx.x * 64;
    const int tid = threadIdx.x;
    const int tx  = tid & 15;    // n-dir (0..15) -> h = tx*4..tx*4+3
    const int ty  = tid >> 4;    // m-dir (0..15) -> m = ty*4..ty*4+3

    float acc[4][4];
#pragma unroll
    for (int i = 0; i < 4; i++)
#pragma unroll
        for (int j = 0; j < 4; j++) acc[i][j] = 0.f;

    for (int k0 = 0; k0 < E_; k0 += BK) {
        // Load 64x32 A tile and 64x32 B tile (transposed into smem).
#pragma unroll
        for (int i = 0; i < 2; i++) {
            int idx = tid + i * 256;        // 0..511
            int row = idx >> 3;             // 0..63
            int c4  = (idx & 7) * 4;        // 0..28
            float4 a = *reinterpret_cast<const float4*>(&x[(size_t)(m0 + row) * E_ + k0 + c4]);
            As[c4 + 0][row] = a.x; As[c4 + 1][row] = a.y;
            As[c4 + 2][row] = a.z; As[c4 + 3][row] = a.w;
            float4 b = *reinterpret_cast<const float4*>(&W[(size_t)row * E_ + k0 + c4]);
            Bs[c4 + 0][row] = b.x; Bs[c4 + 1][row] = b.y;
            Bs[c4 + 2][row] = b.z; Bs[c4 + 3][row] = b.w;
        }
        __syncthreads();

#pragma unroll 16
        for (int kk = 0; kk < BK; kk++) {
            float4 a4 = *reinterpret_cast<const float4*>(&As[kk][ty * 4]);
            float4 b4 = *reinterpret_cast<const float4*>(&Bs[kk][tx * 4]);
            float av[4] = {a4.x, a4.y, a4.z, a4.w};
            float bv[4] = {b4.x, b4.y, b4.z, b4.w};
#pragma unroll
            for (int i = 0; i < 4; i++)
#pragma unroll
                for (int j = 0; j < 4; j++)
                    acc[i][j] = fmaf(av[i], bv[j], acc[i][j]);
        }
        __syncthreads();
    }

#pragma unroll
    for (int i = 0; i < 4; i++) {
        float4 v = make_float4(acc[i][0], acc[i][1], acc[i][2], acc[i][3]);
        *reinterpret_cast<float4*>(&outp[(size_t)(m0 + ty * 4 + i) * H_ + tx * 4]) = v;
    }
}

// ---------------------------------------------------------------------------
// Kernel 2: flash attention (causal, fp32, online softmax).
// grid = (T/64, B), 256 threads. 64-query block per CTA, 64-key blocks.
// Dynamic smem: Qst[64][68] (h-major), Kst[64][68] (h-major),
//               Vs[64][64] (s-major), Ss[64][64] (S then P in-place).
// ---------------------------------------------------------------------------
constexpr int ATTN_SMEM_FLOATS = 2 * 64 * 68 + 2 * 64 * 64;
constexpr int ATTN_SMEM_BYTES  = ATTN_SMEM_FLOATS * 4;   // 67584

__global__ __launch_bounds__(256) void attn_kernel(
    float* __restrict__ out, const int* __restrict__ maskp)
{
    extern __shared__ float sm[];
    float* Qst = sm;                          // [64][68]  Qst[h*68 + m]
    float* Kst = sm + 64 * 68;                // [64][68]  Kst[h*68 + s]
    float* Vs  = sm + 2 * 64 * 68;            // [64][64]  Vs[s*64 + h]
    float* Ss  = sm + 2 * 64 * 68 + 64 * 64;  // [64][64]  Ss[m*64 + s]
    __shared__ float row_m[64], row_l[64], row_a[64];

    const int b    = blockIdx.y;
    const int nblk = gridDim.x;                 // 32
    const int jq   = nblk - 1 - blockIdx.x;     // reversed: heavy blocks first
    const int t0   = jq * 64;
    const int tid  = threadIdx.x;
    const int tx   = tid & 15;                  // h / s direction
    const int ty   = tid >> 4;                  // m direction
    const int lane = tid & 31, warp = tid >> 5;
    const int mask = *maskp;

    const float* qb = g_q + (size_t)b * T_ * H_;
    const float* kb = g_k + (size_t)b * T_ * H_;
    const float* vb = g_v + (size_t)b * T_ * H_;

    // Load Q block transposed (h-major).
#pragma unroll
    for (int i = 0; i < 4; i++) {
        int idx = tid + i * 256;   // 0..1023
        int row = idx >> 4;        // 0..63
        int c4  = (idx & 15) * 4;  // 0..60
        float4 a = *reinterpret_cast<const float4*>(&qb[(size_t)(t0 + row) * H_ + c4]);
        Qst[(c4 + 0) * 68 + row] = a.x; Qst[(c4 + 1) * 68 + row] = a.y;
        Qst[(c4 + 2) * 68 + row] = a.z; Qst[(c4 + 3) * 68 + row] = a.w;
    }
    if (tid < 64) { row_m[tid] = -CUDART_INF_F; row_l[tid] = 0.f; }

    float o[4][4];
#pragma unroll
    for (int i = 0; i < 4; i++)
#pragma unroll
        for (int j = 0; j < 4; j++) o[i][j] = 0.f;

    __syncthreads();

    const int jmax = mask ? jq : (nblk - 1);
    for (int j = 0; j <= jmax; j++) {
        const int s0 = j * 64;

        // Load K (transposed, h-major) and V (natural, s-major).
#pragma unroll
        for (int i = 0; i < 4; i++) {
            int idx = tid + i * 256;
            int row = idx >> 4;
            int c4  = (idx & 15) * 4;
            float4 a = *reinterpret_cast<const float4*>(&kb[(size_t)(s0 + row) * H_ + c4]);
            Kst[(c4 + 0) * 68 + row] = a.x; Kst[(c4 + 1) * 68 + row] = a.y;
            Kst[(c4 + 2) * 68 + row] = a.z; Kst[(c4 + 3) * 68 + row] = a.w;
            float4 v = *reinterpret_cast<const float4*>(&vb[(size_t)(s0 + row) * H_ + c4]);
            *reinterpret_cast<float4*>(&Vs[row * 64 + c4]) = v;
        }
        __syncthreads();

        // S = (Q K^T) * sqrt(H)  (reference multiplies by sqrt(64) = 8)
        float sacc[4][4];
#pragma unroll
        for (int i = 0; i < 4; i++)
#pragma unroll
            for (int jj = 0; jj < 4; jj++) sacc[i][jj] = 0.f;

#pragma unroll 8
        for (int h = 0; h < 64; h++) {
            float4 a4 = *reinterpret_cast<const float4*>(&Qst[h * 68 + ty * 4]);
            float4 b4 = *reinterpret_cast<const float4*>(&Kst[h * 68 + tx * 4]);
            float av[4] = {a4.x, a4.y, a4.z, a4.w};
            float bv[4] = {b4.x, b4.y, b4.z, b4.w};
#pragma unroll
            for (int i = 0; i < 4; i++)
#pragma unroll
                for (int jj = 0; jj < 4; jj++)
                    sacc[i][jj] = fmaf(av[i], bv[jj], sacc[i][jj]);
        }

        const bool diag = (mask != 0) && (j == jq);
#pragma unroll
        for (int i = 0; i < 4; i++) {
            int tg = t0 + ty * 4 + i;
            float vv[4];
#pragma unroll
            for (int jj = 0; jj < 4; jj++) {
                int sg = s0 + tx * 4 + jj;
                float val = sacc[i][jj] * 8.0f;
                if (diag && sg > tg) val = -CUDART_INF_F;
                vv[jj] = val;
            }
            float4 v4 = make_float4(vv[0], vv[1], vv[2], vv[3]);
            *reinterpret_cast<float4*>(&Ss[(ty * 4 + i) * 64 + tx * 4]) = v4;
        }
        __syncthreads();

        // Online softmax: warp w owns rows [8w, 8w+8). In-place S -> P.
#pragma unroll
        for (int r = 0; r < 8; r++) {
            int m = warp * 8 + r;
            float v0 = Ss[m * 64 + lane];
            float v1 = Ss[m * 64 + lane + 32];
            float mx = fmaxf(v0, v1);
#pragma unroll
            for (int off = 16; off > 0; off >>= 1)
                mx = fmaxf(mx, __shfl_xor_sync(0xffffffffu, mx, off));
            float m_old = row_m[m];
            float m_new = fmaxf(m_old, mx);
            float p0 = __expf(v0 - m_new);
            float p1 = __expf(v1 - m_new);
            float sum = p0 + p1;
#pragma unroll
            for (int off = 16; off > 0; off >>= 1)
                sum += __shfl_xor_sync(0xffffffffu, sum, off);
            Ss[m * 64 + lane]      = p0;
            Ss[m * 64 + lane + 32] = p1;
            if (lane == 0) {
                row_a[m] = __expf(m_old - m_new);
                row_l[m] = row_l[m] * row_a[m] + sum;
                row_m[m] = m_new;
            }
        }
        __syncthreads();

        // O = O * alpha + P @ V
        float al[4];
#pragma unroll
        for (int i = 0; i < 4; i++) al[i] = row_a[ty * 4 + i];
#pragma unroll
        for (int i = 0; i < 4; i++)
#pragma unroll
            for (int jj = 0; jj < 4; jj++) o[i][jj] *= al[i];

#pragma unroll 8
        for (int s = 0; s < 64; s++) {
            float p0 = Ss[(ty * 4 + 0) * 64 + s];   // broadcast scalar LDS
            float p1 = Ss[(ty * 4 + 1) * 64 + s];
            float p2 = Ss[(ty * 4 + 2) * 64 + s];
            float p3 = Ss[(ty * 4 + 3) * 64 + s];
            float4 v4 = *reinterpret_cast<const float4*>(&Vs[s * 64 + tx * 4]);
            float vv[4] = {v4.x, v4.y, v4.z, v4.w};
#pragma unroll
            for (int jj = 0; jj < 4; jj++) {
                o[0][jj] = fmaf(p0, vv[jj], o[0][jj]);
                o[1][jj] = fmaf(p1, vv[jj], o[1][jj]);
                o[2][jj] = fmaf(p2, vv[jj], o[2][jj]);
                o[3][jj] = fmaf(p3, vv[jj], o[3][jj]);
            }
        }
        __syncthreads();
    }

    // Normalize and write out[b][t][h]
    float li[4];
#pragma unroll
    for (int i = 0; i < 4; i++) li[i] = 1.0f / row_l[ty * 4 + i];
#pragma unroll
    for (int i = 0; i < 4; i++) {
        float4 v = make_float4(o[i][0] * li[i], o[i][1] * li[i],
                               o[i][2] * li[i], o[i][3] * li[i]);
        *reinterpret_cast<float4*>(&out[((size_t)b * T_ + t0 + ty * 4 + i) * H_ + tx * 4]) = v;
    }
}

// ---------------------------------------------------------------------------
extern "C" void kernel_launch(void* const* d_in, const int* in_sizes, int n_in,
                              void* d_out, int out_size)
{
    const float* x  = (const float*)d_in[0];
    const float* Wq = (const float*)d_in[1];
    const float* Wk = (const float*)d_in[2];
    const float* Wv = (const float*)d_in[3];
    const int* should_mask = (const int*)d_in[4];
    float* out = (float*)d_out;

    // Attribute set is idempotent and not a stream op (capture-safe, no allocs).
    cudaFuncSetAttribute(attn_kernel,
                         cudaFuncAttributeMaxDynamicSharedMemorySize,
                         ATTN_SMEM_BYTES);

    dim3 qkv_grid(MT / 64, 3);
    qkv_kernel<<<qkv_grid, 256>>>(x, Wq, Wk, Wv);

    dim3 attn_grid(T_ / 64, B_);
    attn_kernel<<<attn_grid, 256, ATTN_SMEM_BYTES>>>(out, should_mask);
}

// round 4
// speedup vs baseline: 2.4379x; 2.4379x over previous
#include <cuda_runtime.h>
#include <math.h>
#include <math_constants.h>
#include <cstdint>

// Problem shape (fixed by the reference)
constexpr int B_ = 8;
constexpr int T_ = 2048;
constexpr int E_ = 1024;
constexpr int H_ = 64;
constexpr int MT = B_ * T_;   // 16384 rows

// Scratch for projected q,k,v — device globals (no allocs allowed)
__device__ float g_q[MT * H_];
__device__ float g_k[MT * H_];
__device__ float g_v[MT * H_];

// ===========================================================================
// Baseline-PTX tensor helpers (mma.sync tf32 — assembles at compute_103)
// ===========================================================================
__device__ __forceinline__ float tf32r(float v) {
    uint32_t u;
    asm("cvt.rna.tf32.f32 %0, %1;" : "=r"(u) : "f"(v));
    return __uint_as_float(u);
}
// hi = rna(v); lo = rna(v - hi).  hi*hi + hi*lo + lo*hi ~ fp32 (err ~2^-24)
__device__ __forceinline__ void split4(const float4& v, float4& h, float4& l) {
    h.x = tf32r(v.x); l.x = tf32r(v.x - h.x);
    h.y = tf32r(v.y); l.y = tf32r(v.y - h.y);
    h.z = tf32r(v.z); l.z = tf32r(v.z - h.z);
    h.w = tf32r(v.w); l.w = tf32r(v.w - h.w);
}
__device__ __forceinline__ float4 rnd4(const float4& v) {
    return make_float4(tf32r(v.x), tf32r(v.y), tf32r(v.z), tf32r(v.w));
}
// D += A(16x8) * B(8x8): m16n8k8 tf32, fp32 accumulate
__device__ __forceinline__ void mma8(float* c,
                                     uint32_t a0, uint32_t a1, uint32_t a2, uint32_t a3,
                                     uint32_t b0, uint32_t b1) {
    asm volatile(
        "mma.sync.aligned.m16n8k8.row.col.f32.tf32.tf32.f32 "
        "{%0,%1,%2,%3}, {%4,%5,%6,%7}, {%8,%9}, {%0,%1,%2,%3};"
        : "+f"(c[0]), "+f"(c[1]), "+f"(c[2]), "+f"(c[3])
        : "r"(a0), "r"(a1), "r"(a2), "r"(a3), "r"(b0), "r"(b1));
}
__device__ __forceinline__ uint32_t fu(float v) { return __float_as_uint(v); }

// ===========================================================================
// Kernel 1: QKV projection, tf32 mma.sync.
// out[m][h] = sum_e x[m][e] * W[h][e].  CTA: 128 rows x 64 cols, 8 warps,
// warp = 16 rows x 64 cols.  BK=32 chunks, reg prefetch of next chunk.
// THREE_TERM=true for Wq/Wk (grid.y 0,1), false for Wv (single tf32).
// QPAD=36 (≡4 mod 32): fragment LDS banks (4g + c + 8kt) — conflict-free.
// ===========================================================================
constexpr int QPAD = 36;

template <bool THREE_TERM>
__global__ __launch_bounds__(256, 2) void qkv_mma_kernel(
    const float* __restrict__ x,
    const float* __restrict__ Wq,
    const float* __restrict__ Wk,
    const float* __restrict__ Wv)
{
    extern __shared__ float sq[];
    float* Xhi = sq;                                       // [128][36]
    float* Xlo = THREE_TERM ? Xhi + 128 * QPAD : nullptr;
    float* Bhi = THREE_TERM ? Xlo + 128 * QPAD : Xhi + 128 * QPAD;  // [64][36]
    float* Blo = THREE_TERM ? Bhi + 64 * QPAD : nullptr;

    const float* W = THREE_TERM ? (blockIdx.y == 0 ? Wq : Wk) : Wv;
    float* outp    = THREE_TERM ? (blockIdx.y == 0 ? g_q : g_k) : g_v;

    const int m0   = blockIdx.x * 128;
    const int tid  = threadIdx.x;
    const int warp = tid >> 5, lane = tid & 31;
    const int g = lane >> 2, c = lane & 3;
    const int wb = warp * 16;

    float acc[8][4];
#pragma unroll
    for (int nt = 0; nt < 8; nt++)
#pragma unroll
        for (int i = 0; i < 4; i++) acc[nt][i] = 0.f;

    float4 xr[4], wr[2];
    auto ldg = [&](int k0) {
#pragma unroll
        for (int i = 0; i < 4; i++) {
            int idx = tid + i * 256, r = idx >> 3, c4 = (idx & 7) * 4;
            xr[i] = *reinterpret_cast<const float4*>(&x[(size_t)(m0 + r) * E_ + k0 + c4]);
        }
#pragma unroll
        for (int i = 0; i < 2; i++) {
            int idx = tid + i * 256, r = idx >> 3, c4 = (idx & 7) * 4;
            wr[i] = *reinterpret_cast<const float4*>(&W[(size_t)r * E_ + k0 + c4]);
        }
    };
    auto sts = [&]() {
#pragma unroll
        for (int i = 0; i < 4; i++) {
            int idx = tid + i * 256, r = idx >> 3, c4 = (idx & 7) * 4;
            if (THREE_TERM) {
                float4 h, l; split4(xr[i], h, l);
                *reinterpret_cast<float4*>(&Xhi[r * QPAD + c4]) = h;
                *reinterpret_cast<float4*>(&Xlo[r * QPAD + c4]) = l;
            } else {
                *reinterpret_cast<float4*>(&Xhi[r * QPAD + c4]) = rnd4(xr[i]);
            }
        }
#pragma unroll
        for (int i = 0; i < 2; i++) {
            int idx = tid + i * 256, r = idx >> 3, c4 = (idx & 7) * 4;
            if (THREE_TERM) {
                float4 h, l; split4(wr[i], h, l);
                *reinterpret_cast<float4*>(&Bhi[r * QPAD + c4]) = h;
                *reinterpret_cast<float4*>(&Blo[r * QPAD + c4]) = l;
            } else {
                *reinterpret_cast<float4*>(&Bhi[r * QPAD + c4]) = rnd4(wr[i]);
            }
        }
    };

    ldg(0); sts(); __syncthreads();

    for (int ch = 0; ch < 32; ch++) {
        if (ch < 31) ldg((ch + 1) * 32);   // prefetch next chunk into regs
#pragma unroll
        for (int kt = 0; kt < 4; kt++) {
            const int ka = kt * 8 + c;
            const int ra = (wb + g) * QPAD, rb = (wb + g + 8) * QPAD;
            uint32_t ah0 = fu(Xhi[ra + ka]),     ah1 = fu(Xhi[rb + ka]);
            uint32_t ah2 = fu(Xhi[ra + ka + 4]), ah3 = fu(Xhi[rb + ka + 4]);
            uint32_t al0 = 0, al1 = 0, al2 = 0, al3 = 0;
            if (THREE_TERM) {
                al0 = fu(Xlo[ra + ka]);     al1 = fu(Xlo[rb + ka]);
                al2 = fu(Xlo[ra + ka + 4]); al3 = fu(Xlo[rb + ka + 4]);
            }
#pragma unroll
            for (int nt = 0; nt < 8; nt++) {
                const int br = (nt * 8 + g) * QPAD + ka;
                uint32_t bh0 = fu(Bhi[br]), bh1 = fu(Bhi[br + 4]);
                mma8(acc[nt], ah0, ah1, ah2, ah3, bh0, bh1);
                if (THREE_TERM) {
                    uint32_t bl0 = fu(Blo[br]), bl1 = fu(Blo[br + 4]);
                    mma8(acc[nt], ah0, ah1, ah2, ah3, bl0, bl1);
                    mma8(acc[nt], al0, al1, al2, al3, bh0, bh1);
                }
            }
        }
        __syncthreads();
        if (ch < 31) { sts(); __syncthreads(); }
    }

    const int r0 = m0 + wb + g, r1 = r0 + 8;
#pragma unroll
    for (int nt = 0; nt < 8; nt++) {
        *reinterpret_cast<float2*>(&outp[(size_t)r0 * H_ + nt * 8 + 2 * c]) =
            make_float2(acc[nt][0], acc[nt][1]);
        *reinterpret_cast<float2*>(&outp[(size_t)r1 * H_ + nt * 8 + 2 * c]) =
            make_float2(acc[nt][2], acc[nt][3]);
    }
}

constexpr uint32_t QKV3_SMEM = (128 * QPAD * 2 + 64 * QPAD * 2) * 4;  // 55296
constexpr uint32_t QKV1_SMEM = (128 * QPAD + 64 * QPAD) * 4;          // 27648

// ===========================================================================
// Kernel 2: flash attention, tf32 mma.sync.
// 128 threads (4 warps), 64 queries/CTA, warp = 16 query rows x 64 keys.
// QK^T: 3xTF32 (hi/lo).  PV: single TF32 (P and V rna-rounded).
// Online softmax entirely in registers (rows g, g+8 per thread, quad-reduced).
// Pads: Q/K/P stride 68 (≡4 mod 32), V stride 72 (≡8 mod 32) -> all fragment
// LDS patterns are bank-conflict-free.
// ===========================================================================
constexpr int PADA = 68;
constexpr int PADV = 72;
constexpr uint32_t ATT_SMEM =
    (4 * 64 * PADA + 64 * PADV + 4 * 16 * PADA) * 4;   // 105472 bytes

__global__ __launch_bounds__(128, 2) void attn_mma_kernel(
    float* __restrict__ out, const int* __restrict__ maskp)
{
    extern __shared__ float sa[];
    float* Qhi = sa;                      // [64][68]
    float* Qlo = Qhi + 64 * PADA;
    float* Khi = Qlo + 64 * PADA;
    float* Klo = Khi + 64 * PADA;
    float* Vs  = Klo + 64 * PADA;         // [64][72] (tf32-rounded)
    float* Ps  = Vs  + 64 * PADV;         // 4 x [16][68] warp-private

    const int tid  = threadIdx.x;
    const int warp = tid >> 5, lane = tid & 31;
    const int g = lane >> 2, c = lane & 3;
    const int wb = warp * 16;
    float* Pme = Ps + warp * 16 * PADA;

    // ---- balanced (jq, b) schedule: bids s and s+148 co-resident on one SM.
    // pairs sum to 28 cost-units; 40 singleton SMs get the 28..32-unit rows.
    const int bid = blockIdx.x;
    int jq, b;
    if (bid >= 148) {
        int p = bid - 148;
        if (p < 104) { jq = 26 - (p % 13); b = p / 13; }
        else         { jq = 13;            b = (p - 104) * 2 + 1; }
    } else if (bid >= 108) {
        int s = bid - 108;
        if (s < 32) { jq = 28 + (s >> 3); b = s & 7; }
        else        { jq = 27;            b = s - 32; }
    } else {
        if (bid < 104) { jq = bid % 13; b = bid / 13; }
        else           { jq = 13;       b = (bid - 104) * 2; }
    }
    const int t0   = jq * 64;
    const int mask = *maskp;

    const float* qb = g_q + (size_t)b * T_ * H_;
    const float* kb = g_k + (size_t)b * T_ * H_;
    const float* vb = g_v + (size_t)b * T_ * H_;

    // ---- load Q block (64x64), split hi/lo
#pragma unroll
    for (int i = 0; i < 8; i++) {
        int idx = tid + i * 128, r = idx >> 4, c4 = (idx & 15) * 4;
        float4 v = *reinterpret_cast<const float4*>(&qb[(size_t)(t0 + r) * H_ + c4]);
        float4 h, l; split4(v, h, l);
        *reinterpret_cast<float4*>(&Qhi[r * PADA + c4]) = h;
        *reinterpret_cast<float4*>(&Qlo[r * PADA + c4]) = l;
    }

    float rm[2] = {-CUDART_INF_F, -CUDART_INF_F};
    float rl[2] = {0.f, 0.f};
    float o[8][4];
#pragma unroll
    for (int nt = 0; nt < 8; nt++)
#pragma unroll
        for (int i = 0; i < 4; i++) o[nt][i] = 0.f;

    __syncthreads();

    const int jmax = mask ? jq : 31;
    for (int j = 0; j <= jmax; j++) {
        const int s0 = j * 64;

        // ---- K (hi/lo) and V (tf32-rounded) into smem
#pragma unroll
        for (int i = 0; i < 8; i++) {
            int idx = tid + i * 128, r = idx >> 4, c4 = (idx & 15) * 4;
            float4 kv = *reinterpret_cast<const float4*>(&kb[(size_t)(s0 + r) * H_ + c4]);
            float4 h, l; split4(kv, h, l);
            *reinterpret_cast<float4*>(&Khi[r * PADA + c4]) = h;
            *reinterpret_cast<float4*>(&Klo[r * PADA + c4]) = l;
            float4 vv = *reinterpret_cast<const float4*>(&vb[(size_t)(s0 + r) * H_ + c4]);
            *reinterpret_cast<float4*>(&Vs[r * PADV + c4]) = rnd4(vv);
        }
        __syncthreads();

        // ---- S = Q K^T (3-term tf32)
        float sacc[8][4];
#pragma unroll
        for (int nt = 0; nt < 8; nt++)
#pragma unroll
            for (int i = 0; i < 4; i++) sacc[nt][i] = 0.f;

#pragma unroll
        for (int kt = 0; kt < 8; kt++) {
            const int ka = kt * 8 + c;
            const int ra = (wb + g) * PADA, rb = (wb + g + 8) * PADA;
            uint32_t ah0 = fu(Qhi[ra + ka]),     ah1 = fu(Qhi[rb + ka]);
            uint32_t ah2 = fu(Qhi[ra + ka + 4]), ah3 = fu(Qhi[rb + ka + 4]);
            uint32_t al0 = fu(Qlo[ra + ka]),     al1 = fu(Qlo[rb + ka]);
            uint32_t al2 = fu(Qlo[ra + ka + 4]), al3 = fu(Qlo[rb + ka + 4]);
#pragma unroll
            for (int nt = 0; nt < 8; nt++) {
                const int br = (nt * 8 + g) * PADA + ka;
                uint32_t bh0 = fu(Khi[br]), bh1 = fu(Khi[br + 4]);
                uint32_t bl0 = fu(Klo[br]), bl1 = fu(Klo[br + 4]);
                mma8(sacc[nt], ah0, ah1, ah2, ah3, bh0, bh1);
                mma8(sacc[nt], ah0, ah1, ah2, ah3, bl0, bl1);
                mma8(sacc[nt], al0, al1, al2, al3, bh0, bh1);
            }
        }

        // ---- scale, mask
        const bool diag = (mask != 0) && (j == jq);
#pragma unroll
        for (int nt = 0; nt < 8; nt++) {
#pragma unroll
            for (int e = 0; e < 4; e++) {
                const int sg = s0 + nt * 8 + 2 * c + (e & 1);
                const int tg = t0 + wb + g + (e >> 1) * 8;
                float v = sacc[nt][e] * 8.0f;
                if (diag && sg > tg) v = -CUDART_INF_F;
                sacc[nt][e] = v;
            }
        }

        // ---- online softmax (rows g and g+8; quad = lanes sharing g)
        float alpha[2];
#pragma unroll
        for (int i = 0; i < 2; i++) {
            float m = -CUDART_INF_F;
#pragma unroll
            for (int nt = 0; nt < 8; nt++)
                m = fmaxf(m, fmaxf(sacc[nt][2 * i], sacc[nt][2 * i + 1]));
            m = fmaxf(m, __shfl_xor_sync(0xffffffffu, m, 1));
            m = fmaxf(m, __shfl_xor_sync(0xffffffffu, m, 2));
            const float mnew = fmaxf(rm[i], m);
            alpha[i] = __expf(rm[i] - mnew);
            float s = 0.f;
#pragma unroll
            for (int nt = 0; nt < 8; nt++) {
                float p0 = __expf(sacc[nt][2 * i]     - mnew);
                float p1 = __expf(sacc[nt][2 * i + 1] - mnew);
                sacc[nt][2 * i] = p0; sacc[nt][2 * i + 1] = p1;
                s += p0 + p1;
            }
            s += __shfl_xor_sync(0xffffffffu, s, 1);
            s += __shfl_xor_sync(0xffffffffu, s, 2);
            rl[i] = rl[i] * alpha[i] + s;
            rm[i] = mnew;
        }

        // ---- scale O, write P (tf32-rounded) to warp-private smem
#pragma unroll
        for (int nt = 0; nt < 8; nt++) {
            o[nt][0] *= alpha[0]; o[nt][1] *= alpha[0];
            o[nt][2] *= alpha[1]; o[nt][3] *= alpha[1];
            *reinterpret_cast<float2*>(&Pme[g * PADA + nt * 8 + 2 * c]) =
                make_float2(tf32r(sacc[nt][0]), tf32r(sacc[nt][1]));
            *reinterpret_cast<float2*>(&Pme[(g + 8) * PADA + nt * 8 + 2 * c]) =
                make_float2(tf32r(sacc[nt][2]), tf32r(sacc[nt][3]));
        }
        __syncwarp();

        // ---- O += P V (single tf32)
#pragma unroll
        for (int kt = 0; kt < 8; kt++) {
            const int ka = kt * 8 + c;
            uint32_t a0 = fu(Pme[g * PADA + ka]);
            uint32_t a1 = fu(Pme[(g + 8) * PADA + ka]);
            uint32_t a2 = fu(Pme[g * PADA + ka + 4]);
            uint32_t a3 = fu(Pme[(g + 8) * PADA + ka + 4]);
#pragma unroll
            for (int nt = 0; nt < 8; nt++) {
                uint32_t b0 = fu(Vs[ka * PADV + nt * 8 + g]);
                uint32_t b1 = fu(Vs[(ka + 4) * PADV + nt * 8 + g]);
                mma8(o[nt], a0, a1, a2, a3, b0, b1);
            }
        }
        __syncthreads();   // protect K/V/smem before next iteration overwrite
    }

    // ---- normalize, write out
    const float inv0 = 1.0f / rl[0], inv1 = 1.0f / rl[1];
    const size_t r0 = (size_t)b * T_ + t0 + wb + g;
#pragma unroll
    for (int nt = 0; nt < 8; nt++) {
        *reinterpret_cast<float2*>(&out[r0 * H_ + nt * 8 + 2 * c]) =
            make_float2(o[nt][0] * inv0, o[nt][1] * inv0);
        *reinterpret_cast<float2*>(&out[(r0 + 8) * H_ + nt * 8 + 2 * c]) =
            make_float2(o[nt][2] * inv1, o[nt][3] * inv1);
    }
}

// ---------------------------------------------------------------------------
extern "C" void kernel_launch(void* const* d_in, const int* in_sizes, int n_in,
                              void* d_out, int out_size)
{
    const float* x  = (const float*)d_in[0];
    const float* Wq = (const float*)d_in[1];
    const float* Wk = (const float*)d_in[2];
    const float* Wv = (const float*)d_in[3];
    const int* should_mask = (const int*)d_in[4];
    float* out = (float*)d_out;

    cudaFuncSetAttribute(qkv_mma_kernel<true>,
                         cudaFuncAttributeMaxDynamicSharedMemorySize, QKV3_SMEM);
    cudaFuncSetAttribute(qkv_mma_kernel<false>,
                         cudaFuncAttributeMaxDynamicSharedMemorySize, QKV1_SMEM);
    cudaFuncSetAttribute(attn_mma_kernel,
                         cudaFuncAttributeMaxDynamicSharedMemorySize, ATT_SMEM);

    dim3 qk_grid(MT / 128, 2);
    qkv_mma_kernel<true><<<qk_grid, 256, QKV3_SMEM>>>(x, Wq, Wk, Wv);
    qkv_mma_kernel<false><<<MT / 128, 256, QKV1_SMEM>>>(x, Wq, Wk, Wv);

    attn_mma_kernel<<<256, 128, ATT_SMEM>>>(out, should_mask);
}